// round 14
// baseline (speedup 1.0000x reference)
#include <cuda_runtime.h>
#include <cuda_bf16.h>
#include <stdint.h>
#include <float.h>

#define BSZ    128
#define SDIM   512
#define NMEM   262144
#define CDIM   313
#define TOPK   256
#define KTHRES 0.005f
#define ALPHAV 0.1f
#define EPSV   1e-8f
#define CANDS  4096
#define MARGIN 6e-3f

// ---------------- static device scratch (no allocations) ----------------
__device__ __align__(16) float g_qn[BSZ * SDIM];
__device__ __align__(16) __nv_bfloat16 g_qh[BSZ * SDIM];
__device__ __align__(16) __nv_bfloat16 g_sc16[(size_t)BSZ * NMEM];   // 64 MiB approx scores
__device__ float    g_thresh[BSZ];
__device__ unsigned g_ccnt[BSZ];
__device__ unsigned g_pos[BSZ];
__device__ unsigned g_neg[BSZ];
__device__ __align__(16) int   g_cand_i[BSZ * CANDS];
__device__ __align__(16) float g_cand_s[BSZ * CANDS];

// ---------------- helpers ----------------
static __device__ __forceinline__ unsigned ordu(float f) {
    unsigned u = __float_as_uint(f);
    return (u & 0x80000000u) ? ~u : (u | 0x80000000u);
}
static __device__ __forceinline__ float unord(unsigned u) {
    unsigned b = (u & 0x80000000u) ? (u & 0x7fffffffu) : ~u;
    return __uint_as_float(b);
}
static __device__ __forceinline__ unsigned ord16(unsigned h) {
    h &= 0xFFFFu;
    return (h & 0x8000u) ? ((~h) & 0xFFFFu) : (h | 0x8000u);
}
static __device__ __forceinline__ float bin_lo_f(unsigned o16) {
    unsigned short bits = (o16 & 0x8000u) ? (unsigned short)(o16 & 0x7FFFu)
                                          : (unsigned short)((~o16) & 0xFFFFu);
    __nv_bfloat16 h = *reinterpret_cast<__nv_bfloat16*>(&bits);
    return __bfloat162float(h);
}
static __device__ __forceinline__ float bf_lo(unsigned h) {
    unsigned short bits = (unsigned short)(h & 0xFFFFu);
    __nv_bfloat16 v = *reinterpret_cast<__nv_bfloat16*>(&bits);
    return __bfloat162float(v);
}
static __device__ __forceinline__ uint32_t smem_u32(const void* p) {
    uint32_t a;
    asm("{ .reg .u64 t; cvta.to.shared.u64 t, %1; cvt.u32.u64 %0, t; }" : "=r"(a) : "l"(p));
    return a;
}
#define SWZ128(o) ((o) ^ ((((uint32_t)(o)) >> 3) & 0x70u))

#define LDSM_X4(r0, r1, r2, r3, addr) \
    asm volatile("ldmatrix.sync.aligned.m8n8.x4.shared.b16 {%0,%1,%2,%3}, [%4];" \
                 : "=r"(r0), "=r"(r1), "=r"(r2), "=r"(r3) : "r"(addr))

#define MMA16816(c, a, b0_, b1_) \
    asm volatile("mma.sync.aligned.m16n8k16.row.col.f32.bf16.bf16.f32 " \
                 "{%0,%1,%2,%3}, {%4,%5,%6,%7}, {%8,%9}, {%0,%1,%2,%3};" \
                 : "+f"((c)[0]), "+f"((c)[1]), "+f"((c)[2]), "+f"((c)[3]) \
                 : "r"((a)[0]), "r"((a)[1]), "r"((a)[2]), "r"((a)[3]), \
                   "r"(b0_), "r"(b1_))

// ---------------- K1: normalize q (fp32 + bf16 copies); init per-row state ----------------
__global__ void k_norm(const float* __restrict__ q) {
    __shared__ float red[128];
    int row = blockIdx.x, t = threadIdx.x;
    float ss = 0.f;
    for (int k = t; k < SDIM; k += 128) {
        float v = q[row * SDIM + k];
        ss += v * v;
    }
    red[t] = ss; __syncthreads();
    for (int o = 64; o > 0; o >>= 1) {
        if (t < o) red[t] += red[t + o];
        __syncthreads();
    }
    float inv = 1.0f / sqrtf(red[0]);
    for (int k = t; k < SDIM; k += 128) {
        float v = q[row * SDIM + k] * inv;
        g_qn[row * SDIM + k] = v;
        g_qh[row * SDIM + k] = __float2bfloat16(v);
    }
    if (t == 0) {
        g_ccnt[row] = 0u;
        g_pos[row] = ordu(0.f);
        g_neg[row] = ordu(0.f);
    }
}

// ---------------- K2: bf16 HMMA GEMM with B register prefetch ----------------
// CTA tile: M=128 x N=128; K=512 in chunks of 64. 8 warps, each 32x64.
__global__ void __launch_bounds__(256, 2) k_gemm(const float* __restrict__ key) {
    __shared__ uint8_t sA[128 * 128];   // 128 rows x 64 bf16 (128 B), SW128
    __shared__ uint8_t sB[128 * 128];
    const int t = threadIdx.x, w = t >> 5, l = t & 31;
    const int n0 = blockIdx.x * 128;
    const int m0 = (w & 3) * 32, n0w = (w >> 2) * 64;

    float acc[2][8][4];
#pragma unroll
    for (int i = 0; i < 2; i++)
#pragma unroll
        for (int j = 0; j < 8; j++)
#pragma unroll
            for (int c = 0; c < 4; c++) acc[i][j][c] = 0.f;

    const uint32_t aB = smem_u32(sA), bB = smem_u32(sB);
    const uint32_t aRow0 = (uint32_t)((m0 + (l & 15)) * 128 + (l >> 4) * 16);
    const uint32_t aRow1 = aRow0 + 16 * 128;
    const uint32_t bRowB = (uint32_t)((n0w + (l & 7) + ((l >> 4) & 1) * 8) * 128 +
                                      ((l >> 3) & 1) * 16);

    const int nrow = t >> 1;
    const int half = (t & 1) * 32;
    const float* krBase = key + (size_t)(n0 + nrow) * SDIM + half;

    float4 fB[8];
#pragma unroll
    for (int g4 = 0; g4 < 4; g4++) {
        fB[2 * g4]     = *(const float4*)(krBase + g4 * 8);
        fB[2 * g4 + 1] = *(const float4*)(krBase + g4 * 8 + 4);
    }

    for (int ch = 0; ch < 8; ch++) {
        // A: 128x64 bf16 copy (16 KB) from g_qh (L2-hot)
#pragma unroll
        for (int r = 0; r < 4; r++) {
            int unit = t + r * 256;
            int m = unit >> 3, kb = unit & 7;
            uint4 v = *(const uint4*)((const uint8_t*)g_qh + m * 1024 + ch * 128 + kb * 16);
            *(uint4*)(sA + SWZ128((uint32_t)(m * 128 + kb * 16))) = v;
        }
        // B: convert prefetched fp32 regs -> bf16 SW128 smem
#pragma unroll
        for (int g4 = 0; g4 < 4; g4++) {
            float4 f0 = fB[2 * g4], f1 = fB[2 * g4 + 1];
            __nv_bfloat162 p0 = __float22bfloat162_rn(make_float2(f0.x, f0.y));
            __nv_bfloat162 p1 = __float22bfloat162_rn(make_float2(f0.z, f0.w));
            __nv_bfloat162 p2 = __float22bfloat162_rn(make_float2(f1.x, f1.y));
            __nv_bfloat162 p3 = __float22bfloat162_rn(make_float2(f1.z, f1.w));
            uint4 pv;
            pv.x = *(uint32_t*)&p0; pv.y = *(uint32_t*)&p1;
            pv.z = *(uint32_t*)&p2; pv.w = *(uint32_t*)&p3;
            *(uint4*)(sB + SWZ128((uint32_t)(nrow * 128 + half * 2 + g4 * 16))) = pv;
        }
        // prefetch next chunk's B (overlaps MMA + both barriers)
        if (ch < 7) {
            const float* kr = krBase + (ch + 1) * 64;
#pragma unroll
            for (int g4 = 0; g4 < 4; g4++) {
                fB[2 * g4]     = *(const float4*)(kr + g4 * 8);
                fB[2 * g4 + 1] = *(const float4*)(kr + g4 * 8 + 4);
            }
        }
        __syncthreads();
#pragma unroll
        for (int ks = 0; ks < 4; ks++) {
            const uint32_t kb = (uint32_t)(ks * 32);
            uint32_t a0[4], a1[4];
            LDSM_X4(a0[0], a0[1], a0[2], a0[3], aB + SWZ128(aRow0 + kb));
            LDSM_X4(a1[0], a1[1], a1[2], a1[3], aB + SWZ128(aRow1 + kb));
#pragma unroll
            for (int jj = 0; jj < 4; jj++) {
                uint32_t b[4];
                LDSM_X4(b[0], b[1], b[2], b[3], bB + SWZ128(bRowB + (uint32_t)(jj * 16 * 128) + kb));
                MMA16816(acc[0][2 * jj],     a0, b[0], b[1]);
                MMA16816(acc[0][2 * jj + 1], a0, b[2], b[3]);
                MMA16816(acc[1][2 * jj],     a1, b[0], b[1]);
                MMA16816(acc[1][2 * jj + 1], a1, b[2], b[3]);
            }
        }
        __syncthreads();
    }

    // epilogue: bf16 stores
#pragma unroll
    for (int i = 0; i < 2; i++)
#pragma unroll
        for (int j = 0; j < 8; j++) {
            int row = m0 + i * 16 + (l >> 2);
            int col = n0 + n0w + j * 8 + (l & 3) * 2;
            __nv_bfloat162 v0 = __float22bfloat162_rn(make_float2(acc[i][j][0], acc[i][j][1]));
            __nv_bfloat162 v1 = __float22bfloat162_rn(make_float2(acc[i][j][2], acc[i][j][3]));
            *(__nv_bfloat162*)&g_sc16[(size_t)row * NMEM + col] = v0;
            *(__nv_bfloat162*)&g_sc16[(size_t)(row + 8) * NMEM + col] = v1;
        }
}

// ---------------- K3: radix bin of approx rank-256; margin candidate collection ----------------
__global__ void __launch_bounds__(1024) k_select() {
    __shared__ unsigned hist[8192];
    __shared__ unsigned csum[1024];
    __shared__ unsigned binB;
    const int row = blockIdx.x, t = threadIdx.x, l = t & 31;
    const __nv_bfloat16* s = g_sc16 + (size_t)row * NMEM;

    for (int i = t; i < 8192; i += 1024) hist[i] = 0;
    if (t == 0) binB = 0u;
    __syncthreads();

    // pass 1: histogram with warp-aggregated atomics
    const uint4* sv = (const uint4*)s;
    for (int i = t; i < NMEM / 8; i += 1024) {
        uint4 v = sv[i];
        unsigned hv[8] = { v.x & 0xFFFFu, v.x >> 16, v.y & 0xFFFFu, v.y >> 16,
                           v.z & 0xFFFFu, v.z >> 16, v.w & 0xFFFFu, v.w >> 16 };
#pragma unroll
        for (int j = 0; j < 8; j++) {
            unsigned bin = ord16(hv[j]) >> 3;
            unsigned mask = __match_any_sync(0xffffffffu, bin);
            if (l == (__ffs(mask) - 1))
                atomicAdd(&hist[bin], (unsigned)__popc(mask));
        }
    }
    __syncthreads();

    unsigned loc = 0;
#pragma unroll
    for (int j = 0; j < 8; j++) loc += hist[t * 8 + j];
    csum[t] = loc; __syncthreads();
    for (int off = 1; off < 1024; off <<= 1) {
        unsigned v = (t + off < 1024) ? csum[t + off] : 0u;
        __syncthreads();
        csum[t] += v;
        __syncthreads();
    }
    {
        unsigned S = csum[t];
        if (S >= TOPK && S - loc < TOPK) {
            unsigned c = S - loc;
            for (int b = t * 8 + 7; b >= t * 8; --b) {
                unsigned h = hist[b];
                if (c + h >= TOPK) { binB = (unsigned)b; break; }
                c += h;
            }
        }
    }
    __syncthreads();

    // pass 2: vectorized margin collection
    const float thrF = bin_lo_f(binB << 3) - MARGIN;
    for (int i = t; i < NMEM / 8; i += 1024) {
        uint4 v = sv[i];
        unsigned hv[8] = { v.x & 0xFFFFu, v.x >> 16, v.y & 0xFFFFu, v.y >> 16,
                           v.z & 0xFFFFu, v.z >> 16, v.w & 0xFFFFu, v.w >> 16 };
#pragma unroll
        for (int j = 0; j < 8; j++) {
            if (bf_lo(hv[j]) >= thrF) {
                unsigned p = atomicAdd(&g_ccnt[row], 1u);
                if (p < CANDS) g_cand_i[row * CANDS + p] = i * 8 + j;
            }
        }
    }
}

// ---------------- K4: exact fp32 rescoring of candidates (grid 128x8) ----------------
__global__ void __launch_bounds__(256) k_rescore(const float* __restrict__ key) {
    __shared__ float qs[SDIM];
    const int row = blockIdx.x, t = threadIdx.x;
    const int w = t >> 5, l = t & 31;
    for (int k = t; k < SDIM; k += 256) qs[k] = g_qn[row * SDIM + k];
    __syncthreads();
    const int C = (int)min(g_ccnt[row], (unsigned)CANDS);
    for (int c = blockIdx.y * 8 + w; c < C; c += 64) {
        int idx = g_cand_i[row * CANDS + c];
        const float4* kr = (const float4*)(key + (size_t)idx * SDIM);
        float sum = 0.f;
#pragma unroll
        for (int u = 0; u < 4; u++) {
            float4 v = kr[l + u * 32];
            int k = (l + u * 32) * 4;
            sum += v.x * qs[k] + v.y * qs[k + 1] + v.z * qs[k + 2] + v.w * qs[k + 3];
        }
#pragma unroll
        for (int o = 16; o; o >>= 1) sum += __shfl_xor_sync(0xffffffffu, sum, o);
        if (l == 0) g_cand_s[row * CANDS + c] = sum;
    }
}

// ---------------- K5: exact 256th-largest among candidates ----------------
__global__ void __launch_bounds__(256) k_select2() {
    __shared__ float sc[CANDS];
    const int row = blockIdx.x, t = threadIdx.x;
    const int C = (int)min(g_ccnt[row], (unsigned)CANDS);
    for (int i = t; i < C; i += 256) sc[i] = g_cand_s[row * CANDS + i];
    __syncthreads();
    for (int i = t; i < C; i += 256) {
        float v = sc[i];
        int g = 0, e = 0;
        for (int j = 0; j < C; j++) {
            float wv = sc[j];
            g += (wv > v);
            e += (wv == v);
        }
        if (g < TOPK && g + e >= TOPK) g_thresh[row] = v;
    }
}

// ---------------- K6: KL over selected set, per-row pos/neg max ----------------
__global__ void __launch_bounds__(256) k_kl(const float* __restrict__ cf,
                                            const float* __restrict__ cv) {
    const int row = blockIdx.x;
    const int w = threadIdx.x >> 5, l = threadIdx.x & 31;
    const int C = (int)min(g_ccnt[row], (unsigned)CANDS);
    const float T = g_thresh[row];
    const float* bF = cf + row * CDIM;
    for (int c = blockIdx.y * 8 + w; c < C; c += 64) {
        float sc = g_cand_s[row * CANDS + c];
        if (sc < T) continue;
        const float* a = cv + (size_t)g_cand_i[row * CANDS + c] * CDIM;
        float kl = 0.f;
        for (int j = l; j < CDIM; j += 32) {
            float av = a[j];
            kl += av * log10f(av / (bF[j] + EPSV));
        }
#pragma unroll
        for (int o = 16; o; o >>= 1) kl += __shfl_xor_sync(0xffffffffu, kl, o);
        if (l == 0) {
            if (kl < KTHRES) atomicMax(&g_pos[row], ordu(sc));
            else             atomicMax(&g_neg[row], ordu(sc));
        }
    }
}

// ---------------- K7: hinge + mean ----------------
__global__ void k_final(float* __restrict__ out) {
    __shared__ float red[128];
    int t = threadIdx.x;
    float pos = unord(g_pos[t]), neg = unord(g_neg[t]);
    red[t] = fmaxf(neg - pos + ALPHAV, 0.f);
    __syncthreads();
    for (int o = 64; o > 0; o >>= 1) {
        if (t < o) red[t] += red[t + o];
        __syncthreads();
    }
    if (t == 0) out[0] = red[0] * (1.0f / (float)BSZ);
}

// ---------------- launch ----------------
extern "C" void kernel_launch(void* const* d_in, const int* in_sizes, int n_in,
                              void* d_out, int out_size) {
    const float* query      = (const float*)d_in[0];  // [128, 512]
    const float* color_feat = (const float*)d_in[1];  // [128, 313]
    const float* key        = (const float*)d_in[2];  // [262144, 512]
    const float* color_val  = (const float*)d_in[3];  // [262144, 313]
    float* out = (float*)d_out;

    k_norm<<<BSZ, 128>>>(query);
    k_gemm<<<NMEM / 128, 256>>>(key);
    k_select<<<BSZ, 1024>>>();
    k_rescore<<<dim3(BSZ, 8), 256>>>(key);
    k_select2<<<BSZ, 256>>>();
    k_kl<<<dim3(BSZ, 8), 256>>>(color_feat, color_val);
    k_final<<<1, 128>>>(out);
}

// round 16
// speedup vs baseline: 1.6311x; 1.6311x over previous
#include <cuda_runtime.h>
#include <cuda_bf16.h>
#include <stdint.h>
#include <float.h>

#define BSZ    128
#define SDIM   512
#define NMEM   262144
#define CDIM   313
#define TOPK   256
#define KTHRES 0.005f
#define ALPHAV 0.1f
#define EPSV   1e-8f
#define CANDS  4096
#define MARGIN 6e-3f

// k_gemm dynamic smem layout
#define STAGE_STRIDE 34816           // 128 rows * 272 B (68 floats, padded)
#define SA_OFF  69632                // after 2 stages
#define SB_OFF  86016
#define GEMM_SMEM 102400

// ---------------- static device scratch (no allocations) ----------------
__device__ __align__(16) float g_qn[BSZ * SDIM];
__device__ __align__(16) __nv_bfloat16 g_qh[BSZ * SDIM];
__device__ __align__(16) __nv_bfloat16 g_sc16[(size_t)BSZ * NMEM];   // 64 MiB approx scores
__device__ float    g_thresh[BSZ];
__device__ unsigned g_ccnt[BSZ];
__device__ unsigned g_pos[BSZ];
__device__ unsigned g_neg[BSZ];
__device__ __align__(16) int   g_cand_i[BSZ * CANDS];
__device__ __align__(16) float g_cand_s[BSZ * CANDS];

// ---------------- helpers ----------------
static __device__ __forceinline__ unsigned ordu(float f) {
    unsigned u = __float_as_uint(f);
    return (u & 0x80000000u) ? ~u : (u | 0x80000000u);
}
static __device__ __forceinline__ float unord(unsigned u) {
    unsigned b = (u & 0x80000000u) ? (u & 0x7fffffffu) : ~u;
    return __uint_as_float(b);
}
static __device__ __forceinline__ unsigned ord16(unsigned h) {
    h &= 0xFFFFu;
    return (h & 0x8000u) ? ((~h) & 0xFFFFu) : (h | 0x8000u);
}
static __device__ __forceinline__ float bin_lo_f(unsigned o16) {
    unsigned short bits = (o16 & 0x8000u) ? (unsigned short)(o16 & 0x7FFFu)
                                          : (unsigned short)((~o16) & 0xFFFFu);
    __nv_bfloat16 h = *reinterpret_cast<__nv_bfloat16*>(&bits);
    return __bfloat162float(h);
}
static __device__ __forceinline__ float bf_lo(unsigned h) {
    unsigned short bits = (unsigned short)(h & 0xFFFFu);
    __nv_bfloat16 v = *reinterpret_cast<__nv_bfloat16*>(&bits);
    return __bfloat162float(v);
}
static __device__ __forceinline__ uint32_t smem_u32(const void* p) {
    uint32_t a;
    asm("{ .reg .u64 t; cvta.to.shared.u64 t, %1; cvt.u32.u64 %0, t; }" : "=r"(a) : "l"(p));
    return a;
}
#define SWZ128(o) ((o) ^ ((((uint32_t)(o)) >> 3) & 0x70u))

#define CP_ASYNC16(smaddr, gptr) \
    asm volatile("cp.async.cg.shared.global [%0], [%1], 16;" :: "r"(smaddr), "l"(gptr))
#define CP_COMMIT() asm volatile("cp.async.commit_group;")
#define CP_WAIT(N)  asm volatile("cp.async.wait_group %0;" :: "n"(N))

#define LDSM_X4(r0, r1, r2, r3, addr) \
    asm volatile("ldmatrix.sync.aligned.m8n8.x4.shared.b16 {%0,%1,%2,%3}, [%4];" \
                 : "=r"(r0), "=r"(r1), "=r"(r2), "=r"(r3) : "r"(addr))

#define MMA16816(c, a, b0_, b1_) \
    asm volatile("mma.sync.aligned.m16n8k16.row.col.f32.bf16.bf16.f32 " \
                 "{%0,%1,%2,%3}, {%4,%5,%6,%7}, {%8,%9}, {%0,%1,%2,%3};" \
                 : "+f"((c)[0]), "+f"((c)[1]), "+f"((c)[2]), "+f"((c)[3]) \
                 : "r"((a)[0]), "r"((a)[1]), "r"((a)[2]), "r"((a)[3]), \
                   "r"(b0_), "r"(b1_))

// ---------------- K1: normalize q (fp32 + bf16 copies); init per-row state ----------------
__global__ void k_norm(const float* __restrict__ q) {
    __shared__ float red[128];
    int row = blockIdx.x, t = threadIdx.x;
    float ss = 0.f;
    for (int k = t; k < SDIM; k += 128) {
        float v = q[row * SDIM + k];
        ss += v * v;
    }
    red[t] = ss; __syncthreads();
    for (int o = 64; o > 0; o >>= 1) {
        if (t < o) red[t] += red[t + o];
        __syncthreads();
    }
    float inv = 1.0f / sqrtf(red[0]);
    for (int k = t; k < SDIM; k += 128) {
        float v = q[row * SDIM + k] * inv;
        g_qn[row * SDIM + k] = v;
        g_qh[row * SDIM + k] = __float2bfloat16(v);
    }
    if (t == 0) {
        g_ccnt[row] = 0u;
        g_pos[row] = ordu(0.f);
        g_neg[row] = ordu(0.f);
    }
}

// ---------------- K2: bf16 HMMA GEMM with cp.async double-buffered B staging ----------------
// CTA tile: M=128 x N=128; K=512 in chunks of 64. 8 warps, each 32x64.
__global__ void __launch_bounds__(256, 2) k_gemm(const float* __restrict__ key) {
    extern __shared__ uint8_t sm[];
    uint8_t* sA = sm + SA_OFF;
    uint8_t* sB = sm + SB_OFF;
    const uint32_t smB = smem_u32(sm);
    const int t = threadIdx.x, w = t >> 5, l = t & 31;
    const int n0 = blockIdx.x * 128;
    const int m0 = (w & 3) * 32, n0w = (w >> 2) * 64;

    float acc[2][8][4];
#pragma unroll
    for (int i = 0; i < 2; i++)
#pragma unroll
        for (int j = 0; j < 8; j++)
#pragma unroll
            for (int c = 0; c < 4; c++) acc[i][j][c] = 0.f;

    const uint32_t aB = smB + SA_OFF, bB = smB + SB_OFF;
    const uint32_t aRow0 = (uint32_t)((m0 + (l & 15)) * 128 + (l >> 4) * 16);
    const uint32_t aRow1 = aRow0 + 16 * 128;
    const uint32_t bRowB = (uint32_t)((n0w + (l & 7) + ((l >> 4) & 1) * 8) * 128 +
                                      ((l >> 3) & 1) * 16);

    const int nrow  = t >> 1;              // B row this thread stages/converts
    const int hStg  = (t & 1) * 128;       // byte offset of 32-float half in fp32 staging row
    const int hBf   = (t & 1) * 64;        // byte offset of same half in bf16 tile row
    const float* krBase = key + (size_t)(n0 + nrow) * SDIM + (t & 1) * 32;

    // prologue: stage chunk 0
    {
        uint32_t dst = smB + (uint32_t)(nrow * 272 + hStg);
        const float* src = krBase;
#pragma unroll
        for (int s = 0; s < 8; s++) CP_ASYNC16(dst + s * 16, src + s * 4);
        CP_COMMIT();
    }

    for (int ch = 0; ch < 8; ch++) {
        if (ch < 7) {
            uint32_t dst = smB + ((ch + 1) & 1) * STAGE_STRIDE + (uint32_t)(nrow * 272 + hStg);
            const float* src = krBase + (ch + 1) * 64;
#pragma unroll
            for (int s = 0; s < 8; s++) CP_ASYNC16(dst + s * 16, src + s * 4);
            CP_COMMIT();
            CP_WAIT(1);
        } else {
            CP_WAIT(0);
        }
        __syncthreads();   // staged chunk ch visible to all; sA/sB free (post-MMA barrier)

        // A: 128x64 bf16 copy from g_qh (L2-hot)
#pragma unroll
        for (int r = 0; r < 4; r++) {
            int unit = t + r * 256;
            int m = unit >> 3, kb = unit & 7;
            uint4 v = *(const uint4*)((const uint8_t*)g_qh + m * 1024 + ch * 128 + kb * 16);
            *(uint4*)(sA + SWZ128((uint32_t)(m * 128 + kb * 16))) = v;
        }
        // B: convert staged fp32 -> bf16 SW128 smem
        {
            const uint8_t* st = sm + (ch & 1) * STAGE_STRIDE + nrow * 272 + hStg;
#pragma unroll
            for (int g4 = 0; g4 < 4; g4++) {
                float4 f0 = *(const float4*)(st + g4 * 32);
                float4 f1 = *(const float4*)(st + g4 * 32 + 16);
                __nv_bfloat162 p0 = __float22bfloat162_rn(make_float2(f0.x, f0.y));
                __nv_bfloat162 p1 = __float22bfloat162_rn(make_float2(f0.z, f0.w));
                __nv_bfloat162 p2 = __float22bfloat162_rn(make_float2(f1.x, f1.y));
                __nv_bfloat162 p3 = __float22bfloat162_rn(make_float2(f1.z, f1.w));
                uint4 pv;
                pv.x = *(uint32_t*)&p0; pv.y = *(uint32_t*)&p1;
                pv.z = *(uint32_t*)&p2; pv.w = *(uint32_t*)&p3;
                *(uint4*)(sB + SWZ128((uint32_t)(nrow * 128 + hBf + g4 * 16))) = pv;
            }
        }
        __syncthreads();

#pragma unroll
        for (int ks = 0; ks < 4; ks++) {
            const uint32_t kb = (uint32_t)(ks * 32);
            uint32_t a0[4], a1[4];
            LDSM_X4(a0[0], a0[1], a0[2], a0[3], aB + SWZ128(aRow0 + kb));
            LDSM_X4(a1[0], a1[1], a1[2], a1[3], aB + SWZ128(aRow1 + kb));
#pragma unroll
            for (int jj = 0; jj < 4; jj++) {
                uint32_t b[4];
                LDSM_X4(b[0], b[1], b[2], b[3], bB + SWZ128(bRowB + (uint32_t)(jj * 16 * 128) + kb));
                MMA16816(acc[0][2 * jj],     a0, b[0], b[1]);
                MMA16816(acc[0][2 * jj + 1], a0, b[2], b[3]);
                MMA16816(acc[1][2 * jj],     a1, b[0], b[1]);
                MMA16816(acc[1][2 * jj + 1], a1, b[2], b[3]);
            }
        }
        __syncthreads();
    }

    // epilogue: bf16 stores
#pragma unroll
    for (int i = 0; i < 2; i++)
#pragma unroll
        for (int j = 0; j < 8; j++) {
            int row = m0 + i * 16 + (l >> 2);
            int col = n0 + n0w + j * 8 + (l & 3) * 2;
            __nv_bfloat162 v0 = __float22bfloat162_rn(make_float2(acc[i][j][0], acc[i][j][1]));
            __nv_bfloat162 v1 = __float22bfloat162_rn(make_float2(acc[i][j][2], acc[i][j][3]));
            *(__nv_bfloat162*)&g_sc16[(size_t)row * NMEM + col] = v0;
            *(__nv_bfloat162*)&g_sc16[(size_t)(row + 8) * NMEM + col] = v1;
        }
}

// ---------------- K3: radix bin of approx rank-256; margin candidate collection ----------------
__global__ void __launch_bounds__(1024) k_select() {
    __shared__ unsigned hist[8192];
    __shared__ unsigned csum[1024];
    __shared__ unsigned binB;
    const int row = blockIdx.x, t = threadIdx.x;
    const __nv_bfloat16* s = g_sc16 + (size_t)row * NMEM;

    for (int i = t; i < 8192; i += 1024) hist[i] = 0;
    if (t == 0) binB = 0u;
    __syncthreads();

    // pass 1: vectorized histogram, plain smem atomics (R13-proven)
    const uint4* sv = (const uint4*)s;
    for (int i = t; i < NMEM / 8; i += 1024) {
        uint4 v = sv[i];
        atomicAdd(&hist[ord16(v.x) >> 3], 1u);
        atomicAdd(&hist[ord16(v.x >> 16) >> 3], 1u);
        atomicAdd(&hist[ord16(v.y) >> 3], 1u);
        atomicAdd(&hist[ord16(v.y >> 16) >> 3], 1u);
        atomicAdd(&hist[ord16(v.z) >> 3], 1u);
        atomicAdd(&hist[ord16(v.z >> 16) >> 3], 1u);
        atomicAdd(&hist[ord16(v.w) >> 3], 1u);
        atomicAdd(&hist[ord16(v.w >> 16) >> 3], 1u);
    }
    __syncthreads();

    unsigned loc = 0;
#pragma unroll
    for (int j = 0; j < 8; j++) loc += hist[t * 8 + j];
    csum[t] = loc; __syncthreads();
    for (int off = 1; off < 1024; off <<= 1) {
        unsigned v = (t + off < 1024) ? csum[t + off] : 0u;
        __syncthreads();
        csum[t] += v;
        __syncthreads();
    }
    {
        unsigned S = csum[t];
        if (S >= TOPK && S - loc < TOPK) {
            unsigned c = S - loc;
            for (int b = t * 8 + 7; b >= t * 8; --b) {
                unsigned h = hist[b];
                if (c + h >= TOPK) { binB = (unsigned)b; break; }
                c += h;
            }
        }
    }
    __syncthreads();

    // pass 2: vectorized margin collection
    const float thrF = bin_lo_f(binB << 3) - MARGIN;
    for (int i = t; i < NMEM / 8; i += 1024) {
        uint4 v = sv[i];
        unsigned hv[8] = { v.x & 0xFFFFu, v.x >> 16, v.y & 0xFFFFu, v.y >> 16,
                           v.z & 0xFFFFu, v.z >> 16, v.w & 0xFFFFu, v.w >> 16 };
#pragma unroll
        for (int j = 0; j < 8; j++) {
            if (bf_lo(hv[j]) >= thrF) {
                unsigned p = atomicAdd(&g_ccnt[row], 1u);
                if (p < CANDS) g_cand_i[row * CANDS + p] = i * 8 + j;
            }
        }
    }
}

// ---------------- K4: exact fp32 rescoring of candidates (grid 128x16) ----------------
__global__ void __launch_bounds__(256) k_rescore(const float* __restrict__ key) {
    __shared__ float qs[SDIM];
    const int row = blockIdx.x, t = threadIdx.x;
    const int w = t >> 5, l = t & 31;
    for (int k = t; k < SDIM; k += 256) qs[k] = g_qn[row * SDIM + k];
    __syncthreads();
    const int C = (int)min(g_ccnt[row], (unsigned)CANDS);
    for (int c = blockIdx.y * 8 + w; c < C; c += 128) {
        int idx = g_cand_i[row * CANDS + c];
        const float4* kr = (const float4*)(key + (size_t)idx * SDIM);
        float sum = 0.f;
#pragma unroll
        for (int u = 0; u < 4; u++) {
            float4 v = kr[l + u * 32];
            int k = (l + u * 32) * 4;
            sum += v.x * qs[k] + v.y * qs[k + 1] + v.z * qs[k + 2] + v.w * qs[k + 3];
        }
#pragma unroll
        for (int o = 16; o; o >>= 1) sum += __shfl_xor_sync(0xffffffffu, sum, o);
        if (l == 0) g_cand_s[row * CANDS + c] = sum;
    }
}

// ---------------- K5: exact 256th-largest among candidates ----------------
__global__ void __launch_bounds__(256) k_select2() {
    __shared__ float sc[CANDS];
    const int row = blockIdx.x, t = threadIdx.x;
    const int C = (int)min(g_ccnt[row], (unsigned)CANDS);
    for (int i = t; i < C; i += 256) sc[i] = g_cand_s[row * CANDS + i];
    __syncthreads();
    for (int i = t; i < C; i += 256) {
        float v = sc[i];
        int g = 0, e = 0;
        for (int j = 0; j < C; j++) {
            float wv = sc[j];
            g += (wv > v);
            e += (wv == v);
        }
        if (g < TOPK && g + e >= TOPK) g_thresh[row] = v;
    }
}

// ---------------- K6: KL over selected set, per-row pos/neg max ----------------
__global__ void __launch_bounds__(256) k_kl(const float* __restrict__ cf,
                                            const float* __restrict__ cv) {
    const int row = blockIdx.x;
    const int w = threadIdx.x >> 5, l = threadIdx.x & 31;
    const int C = (int)min(g_ccnt[row], (unsigned)CANDS);
    const float T = g_thresh[row];
    const float* bF = cf + row * CDIM;
    for (int c = blockIdx.y * 8 + w; c < C; c += 64) {
        float sc = g_cand_s[row * CANDS + c];
        if (sc < T) continue;
        const float* a = cv + (size_t)g_cand_i[row * CANDS + c] * CDIM;
        float kl = 0.f;
        for (int j = l; j < CDIM; j += 32) {
            float av = a[j];
            kl += av * log10f(av / (bF[j] + EPSV));
        }
#pragma unroll
        for (int o = 16; o; o >>= 1) kl += __shfl_xor_sync(0xffffffffu, kl, o);
        if (l == 0) {
            if (kl < KTHRES) atomicMax(&g_pos[row], ordu(sc));
            else             atomicMax(&g_neg[row], ordu(sc));
        }
    }
}

// ---------------- K7: hinge + mean ----------------
__global__ void k_final(float* __restrict__ out) {
    __shared__ float red[128];
    int t = threadIdx.x;
    float pos = unord(g_pos[t]), neg = unord(g_neg[t]);
    red[t] = fmaxf(neg - pos + ALPHAV, 0.f);
    __syncthreads();
    for (int o = 64; o > 0; o >>= 1) {
        if (t < o) red[t] += red[t + o];
        __syncthreads();
    }
    if (t == 0) out[0] = red[0] * (1.0f / (float)BSZ);
}

// ---------------- launch ----------------
extern "C" void kernel_launch(void* const* d_in, const int* in_sizes, int n_in,
                              void* d_out, int out_size) {
    const float* query      = (const float*)d_in[0];  // [128, 512]
    const float* color_feat = (const float*)d_in[1];  // [128, 313]
    const float* key        = (const float*)d_in[2];  // [262144, 512]
    const float* color_val  = (const float*)d_in[3];  // [262144, 313]
    float* out = (float*)d_out;

    cudaFuncSetAttribute(k_gemm, cudaFuncAttributeMaxDynamicSharedMemorySize, GEMM_SMEM);

    k_norm<<<BSZ, 128>>>(query);
    k_gemm<<<NMEM / 128, 256, GEMM_SMEM>>>(key);
    k_select<<<BSZ, 1024>>>();
    k_rescore<<<dim3(BSZ, 16), 256>>>(key);
    k_select2<<<BSZ, 256>>>();
    k_kl<<<dim3(BSZ, 8), 256>>>(color_feat, color_val);
    k_final<<<1, 128>>>(out);
}